// round 8
// baseline (speedup 1.0000x reference)
#include <cuda_runtime.h>
#include <cuda_bf16.h>
#include <math.h>
#include <stdint.h>

// Problem constants
#define BATCH 64
#define NP 24
#define NPAT 576
#define DH 768
#define KDIM 768
#define LLAT 1024
#define HW 384
#define PSZ 16
#define TAU_INV 2.0f
#define EPSN 1e-8f
#define MTOT (BATCH*NPAT) // 36864

// GEMM tiling: 64x128 block tile, 4 warps of 32x64, BK=32, 3-stage cp.async
#define BM 64
#define BN 128
#define BKC 32
#define BKP 40            // padded smem row stride (bf16): conflict-free LDSM
#define NTHR 128
#define STAGES 3
#define ASTG (BM * BKP * 2)   // 5120 B per A stage
#define BSTG (BN * BKP * 2)   // 10240 B per B stage

// Scratch
__device__ __nv_bfloat16 g_Ah[(size_t)MTOT * KDIM];        // im2col bf16
__device__ __nv_bfloat16 g_Wh[(size_t)DH * KDIM];          // conv weight bf16
__device__ float         g_pn[(size_t)MTOT * DH];          // embeddings fp32
__device__ __nv_bfloat16 g_pnh[(size_t)(MTOT + 128) * DH]; // normalized bf16 (+pad)
__device__ __nv_bfloat16 g_lnh[(size_t)LLAT * DH];         // normalized latent bf16
__device__ double g_far[BATCH];
__device__ double g_close[BATCH];

// ---------------------------------------------------------------- PTX helpers
__device__ __forceinline__ void mma16816(float c[4],
    uint32_t a0, uint32_t a1, uint32_t a2, uint32_t a3,
    uint32_t b0, uint32_t b1)
{
    asm volatile(
        "mma.sync.aligned.m16n8k16.row.col.f32.bf16.bf16.f32 "
        "{%0,%1,%2,%3}, {%4,%5,%6,%7}, {%8,%9}, {%0,%1,%2,%3};\n"
        : "+f"(c[0]), "+f"(c[1]), "+f"(c[2]), "+f"(c[3])
        : "r"(a0), "r"(a1), "r"(a2), "r"(a3), "r"(b0), "r"(b1));
}
__device__ __forceinline__ void cpa16(uint32_t dst, const void* src) {
    asm volatile("cp.async.cg.shared.global [%0], [%1], 16;\n" :: "r"(dst), "l"(src));
}
__device__ __forceinline__ void cp_commit() { asm volatile("cp.async.commit_group;\n"); }
__device__ __forceinline__ void cp_wait0()  { asm volatile("cp.async.wait_group 0;\n"); }
__device__ __forceinline__ void cp_wait1()  { asm volatile("cp.async.wait_group 1;\n"); }
__device__ __forceinline__ void ldsm4(uint32_t& r0, uint32_t& r1, uint32_t& r2, uint32_t& r3,
                                      uint32_t addr)
{
    asm volatile("ldmatrix.sync.aligned.m8n8.x4.shared.b16 {%0,%1,%2,%3}, [%4];\n"
                 : "=r"(r0), "=r"(r1), "=r"(r2), "=r"(r3) : "r"(addr));
}

// ---------------------------------------------------------------- stage loader
// A: 64 rows x 32 k, B: 128 rows x 32 k, both bf16 K-major
__device__ __forceinline__ void load_stage(uint32_t sAu, uint32_t sBu, int stage,
    const __nv_bfloat16* aG, int ldA,
    const __nv_bfloat16* bG, int ldB, int k0, int tid)
{
    uint32_t aBase = sAu + (uint32_t)stage * ASTG;
    uint32_t bBase = sBu + (uint32_t)stage * BSTG;
    #pragma unroll
    for (int it = 0; it < 2; it++) {
        int idx = tid + it * NTHR;            // 0..255
        int row = idx >> 2, slot = idx & 3;
        cpa16(aBase + (uint32_t)(row * BKP + slot * 8) * 2,
              aG + (size_t)row * ldA + k0 + slot * 8);
    }
    #pragma unroll
    for (int it = 0; it < 4; it++) {
        int idx = tid + it * NTHR;            // 0..511
        int row = idx >> 2, slot = idx & 3;
        cpa16(bBase + (uint32_t)(row * BKP + slot * 8) * 2,
              bG + (size_t)row * ldB + k0 + slot * 8);
    }
}

// ---------------------------------------------------------------- mainloop
// 64x128 block tile, warp tile 32x64, 3-stage pipeline, nk chunks of K=32
__device__ __forceinline__ void mainloop(
    const __nv_bfloat16* __restrict__ aG, int ldA,
    const __nv_bfloat16* __restrict__ bG, int ldB,
    int nk, uint32_t sAu, uint32_t sBu, float acc[2][8][4])
{
    int tid  = threadIdx.x;
    int lane = tid & 31, warp = tid >> 5;
    int wm = (warp >> 1) * 32;     // 0,32
    int wn = (warp & 1) * 64;      // 0,64
    int arow  = lane & 15;
    int acol8 = (lane >> 4) * 8;
    int bn  = ((lane >> 4) & 1) * 8 + (lane & 7);
    int bk8 = ((lane >> 3) & 1) * 8;

    uint32_t aAddr[2], bAddr[4];
    #pragma unroll
    for (int mi = 0; mi < 2; mi++)
        aAddr[mi] = sAu + (uint32_t)((wm + mi * 16 + arow) * BKP + acol8) * 2;
    #pragma unroll
    for (int p = 0; p < 4; p++)
        bAddr[p] = sBu + (uint32_t)((wn + p * 16 + bn) * BKP + bk8) * 2;

    load_stage(sAu, sBu, 0, aG, ldA, bG, ldB, 0, tid); cp_commit();
    load_stage(sAu, sBu, 1, aG, ldA, bG, ldB, BKC, tid); cp_commit();

    int stage = 0;
    for (int kc = 0; kc < nk; kc++) {
        if (kc >= nk - 2) cp_wait0(); else cp_wait1();
        __syncthreads();
        if (kc + 2 < nk) {
            int ns = stage + 2; if (ns >= STAGES) ns -= STAGES;
            load_stage(sAu, sBu, ns, aG, ldA, bG, ldB, (kc + 2) * BKC, tid);
            cp_commit();
        }
        uint32_t aoff = (uint32_t)stage * ASTG;
        uint32_t boff = (uint32_t)stage * BSTG;
        #pragma unroll
        for (int ks = 0; ks < 2; ks++) {
            uint32_t ko2 = (uint32_t)(ks * 16) * 2;
            uint32_t a[2][4], b[8][2];
            #pragma unroll
            for (int mi = 0; mi < 2; mi++)
                ldsm4(a[mi][0], a[mi][1], a[mi][2], a[mi][3], aAddr[mi] + aoff + ko2);
            #pragma unroll
            for (int p = 0; p < 4; p++)
                ldsm4(b[p*2][0], b[p*2][1], b[p*2+1][0], b[p*2+1][1], bAddr[p] + boff + ko2);
            #pragma unroll
            for (int mi = 0; mi < 2; mi++)
                #pragma unroll
                for (int nj = 0; nj < 8; nj++)
                    mma16816(acc[mi][nj], a[mi][0], a[mi][1], a[mi][2], a[mi][3],
                             b[nj][0], b[nj][1]);
        }
        if (++stage == STAGES) stage = 0;
    }
}

// block reduce (128 threads) -> double atomic
__device__ __forceinline__ void block_reduce_add(float part, float* red, double* gout) {
    int tid = threadIdx.x, lane = tid & 31, warp = tid >> 5;
    #pragma unroll
    for (int o = 16; o; o >>= 1) part += __shfl_xor_sync(0xffffffffu, part, o);
    if (lane == 0) red[warp] = part;
    __syncthreads();
    if (tid == 0) {
        float s = red[0] + red[1] + red[2] + red[3];
        atomicAdd(gout, (double)s);
    }
}

// ---------------------------------------------------------------- init
__global__ void init_k() {
    int t = threadIdx.x;
    if (t < BATCH) { g_far[t] = 0.0; g_close[t] = 0.0; }
}

// ---------------------------------------------------------------- im2col -> bf16
__global__ void im2col_k(const float* __restrict__ x) {
    int idx = blockIdx.x * 256 + threadIdx.x;
    int kq  = idx % (KDIM / 8);
    int row = idx / (KDIM / 8);
    int k  = kq * 8;
    int kw = k & 15, kh = (k >> 4) & 15, c = k >> 8;
    int pw = row % NP; int t = row / NP; int ph = t % NP; int b = t / NP;
    const float* src = x + ((size_t)(b*3 + c)*HW + ph*PSZ + kh)*HW + pw*PSZ + kw;
    float4 v0 = *(const float4*)(src);
    float4 v1 = *(const float4*)(src + 4);
    __nv_bfloat16 o[8];
    o[0]=__float2bfloat16_rn(v0.x); o[1]=__float2bfloat16_rn(v0.y);
    o[2]=__float2bfloat16_rn(v0.z); o[3]=__float2bfloat16_rn(v0.w);
    o[4]=__float2bfloat16_rn(v1.x); o[5]=__float2bfloat16_rn(v1.y);
    o[6]=__float2bfloat16_rn(v1.z); o[7]=__float2bfloat16_rn(v1.w);
    *(int4*)(g_Ah + (size_t)row * KDIM + k) = *(int4*)o;
}

// ---------------------------------------------------------------- W -> bf16
__global__ void wconv_k(const float* __restrict__ W) {
    int idx = blockIdx.x * 256 + threadIdx.x;
    const float4* src = (const float4*)(W + (size_t)idx * 8);
    float4 v0 = src[0], v1 = src[1];
    __nv_bfloat16 o[8];
    o[0]=__float2bfloat16_rn(v0.x); o[1]=__float2bfloat16_rn(v0.y);
    o[2]=__float2bfloat16_rn(v0.z); o[3]=__float2bfloat16_rn(v0.w);
    o[4]=__float2bfloat16_rn(v1.x); o[5]=__float2bfloat16_rn(v1.y);
    o[6]=__float2bfloat16_rn(v1.z); o[7]=__float2bfloat16_rn(v1.w);
    *(int4*)(g_Wh + (size_t)idx * 8) = *(int4*)o;
}

// ---------------------------------------------------------------- GEMM embed
__global__ __launch_bounds__(NTHR, 4) void gemm_embed_k(const float* __restrict__ bias) {
    __shared__ __align__(16) __nv_bfloat16 sA[STAGES * BM * BKP];
    __shared__ __align__(16) __nv_bfloat16 sB[STAGES * BN * BKP];
    uint32_t sAu = (uint32_t)__cvta_generic_to_shared(sA);
    uint32_t sBu = (uint32_t)__cvta_generic_to_shared(sB);
    const __nv_bfloat16* aG = g_Ah + (size_t)blockIdx.x * BM * KDIM;
    const __nv_bfloat16* bG = g_Wh + (size_t)blockIdx.y * BN * KDIM;
    float acc[2][8][4] = {};
    mainloop(aG, KDIM, bG, KDIM, KDIM / BKC, sAu, sBu, acc);

    int lane = threadIdx.x & 31, warp = threadIdx.x >> 5;
    int wm = (warp >> 1) * 32, wn = (warp & 1) * 64;
    int g = lane >> 2, lt = lane & 3;
    int rowB = blockIdx.x * BM + wm;
    int colB = blockIdx.y * BN + wn;
    #pragma unroll
    for (int mi = 0; mi < 2; mi++)
        #pragma unroll
        for (int nj = 0; nj < 8; nj++) {
            int col = colB + nj * 8 + lt * 2;
            float b0 = bias[col], b1 = bias[col + 1];
            int r0 = rowB + mi * 16 + g;
            float2 v0 = { acc[mi][nj][0] + b0, acc[mi][nj][1] + b1 };
            float2 v1 = { acc[mi][nj][2] + b0, acc[mi][nj][3] + b1 };
            *(float2*)(g_pn + (size_t)r0 * DH + col)       = v0;
            *(float2*)(g_pn + (size_t)(r0 + 8) * DH + col) = v1;
        }
}

// ---------------------------------------------------------------- L2 normalize
__global__ void norm_patch_k() {
    int gw = (blockIdx.x * blockDim.x + threadIdx.x) >> 5;
    int lane = threadIdx.x & 31;
    if (gw >= MTOT) return;
    const float4* r = (const float4*)(g_pn + (size_t)gw * DH);
    ushort4* dst = (ushort4*)(g_pnh + (size_t)gw * DH);
    float s = 0.f; float4 v[6];
    #pragma unroll
    for (int i = 0; i < 6; i++) {
        v[i] = r[lane + 32*i];
        s += v[i].x*v[i].x + v[i].y*v[i].y + v[i].z*v[i].z + v[i].w*v[i].w;
    }
    #pragma unroll
    for (int o = 16; o; o >>= 1) s += __shfl_xor_sync(0xffffffffu, s, o);
    float inv = 1.0f / fmaxf(sqrtf(s), EPSN);
    #pragma unroll
    for (int i = 0; i < 6; i++) {
        __nv_bfloat16 o4[4];
        o4[0] = __float2bfloat16_rn(v[i].x * inv);
        o4[1] = __float2bfloat16_rn(v[i].y * inv);
        o4[2] = __float2bfloat16_rn(v[i].z * inv);
        o4[3] = __float2bfloat16_rn(v[i].w * inv);
        dst[lane + 32*i] = *(ushort4*)o4;
    }
}

__global__ void norm_latent_k(const float* __restrict__ latent) {
    int gw = (blockIdx.x * blockDim.x + threadIdx.x) >> 5;
    int lane = threadIdx.x & 31;
    if (gw >= LLAT) return;
    const float4* src = (const float4*)(latent + (size_t)gw * DH);
    ushort4* dst = (ushort4*)(g_lnh + (size_t)gw * DH);
    float s = 0.f; float4 v[6];
    #pragma unroll
    for (int i = 0; i < 6; i++) {
        v[i] = src[lane + 32*i];
        s += v[i].x*v[i].x + v[i].y*v[i].y + v[i].z*v[i].z + v[i].w*v[i].w;
    }
    #pragma unroll
    for (int o = 16; o; o >>= 1) s += __shfl_xor_sync(0xffffffffu, s, o);
    float inv = 1.0f / fmaxf(sqrtf(s), EPSN);
    #pragma unroll
    for (int i = 0; i < 6; i++) {
        __nv_bfloat16 o4[4];
        o4[0] = __float2bfloat16_rn(v[i].x * inv);
        o4[1] = __float2bfloat16_rn(v[i].y * inv);
        o4[2] = __float2bfloat16_rn(v[i].z * inv);
        o4[3] = __float2bfloat16_rn(v[i].w * inv);
        dst[lane + 32*i] = *(ushort4*)o4;
    }
}

// ---------------------------------------------------------------- far
// per-batch 576x576: 9 row-tiles (64) x 5 col-tiles (128, masked), exclude diag
__global__ __launch_bounds__(NTHR, 4) void far_k() {
    int tI = blockIdx.x, tJ = blockIdx.y, b = blockIdx.z;
    __shared__ __align__(16) __nv_bfloat16 sA[STAGES * BM * BKP];
    __shared__ __align__(16) __nv_bfloat16 sB[STAGES * BN * BKP];
    __shared__ float red[4];
    uint32_t sAu = (uint32_t)__cvta_generic_to_shared(sA);
    uint32_t sBu = (uint32_t)__cvta_generic_to_shared(sB);
    const __nv_bfloat16* aG = g_pnh + ((size_t)b * NPAT + tI * BM) * DH;
    const __nv_bfloat16* bG = g_pnh + ((size_t)b * NPAT + tJ * BN) * DH;
    float acc[2][8][4] = {};
    mainloop(aG, DH, bG, DH, DH / BKC, sAu, sBu, acc);

    int lane = threadIdx.x & 31, warp = threadIdx.x >> 5;
    int wm = (warp >> 1) * 32, wn = (warp & 1) * 64;
    int g = lane >> 2, lt = lane & 3;
    float part = 0.f;
    #pragma unroll
    for (int mi = 0; mi < 2; mi++)
        #pragma unroll
        for (int nj = 0; nj < 8; nj++) {
            int r0 = tI * BM + wm + mi * 16 + g;       // row within batch (<576 always)
            int c0 = tJ * BN + wn + nj * 8 + lt * 2;   // col within batch (mask >=576)
            float e0 = __expf(acc[mi][nj][0] * TAU_INV);
            float e1 = __expf(acc[mi][nj][1] * TAU_INV);
            float e2 = __expf(acc[mi][nj][2] * TAU_INV);
            float e3 = __expf(acc[mi][nj][3] * TAU_INV);
            part += (c0     < NPAT && r0     != c0    ) ? e0 : 0.f;
            part += (c0 + 1 < NPAT && r0     != c0 + 1) ? e1 : 0.f;
            part += (c0     < NPAT && r0 + 8 != c0    ) ? e2 : 0.f;
            part += (c0 + 1 < NPAT && r0 + 8 != c0 + 1) ? e3 : 0.f;
        }
    block_reduce_add(part, red, &g_far[b]);
}

// ---------------------------------------------------------------- close
// 36864 x 1024 GEMM; each 64-row tile lies in exactly one batch (576 = 9*64)
__global__ __launch_bounds__(NTHR, 4) void close_k() {
    __shared__ __align__(16) __nv_bfloat16 sA[STAGES * BM * BKP];
    __shared__ __align__(16) __nv_bfloat16 sB[STAGES * BN * BKP];
    __shared__ float red[4];
    uint32_t sAu = (uint32_t)__cvta_generic_to_shared(sA);
    uint32_t sBu = (uint32_t)__cvta_generic_to_shared(sB);
    const __nv_bfloat16* aG = g_pnh + (size_t)blockIdx.x * BM * DH;
    const __nv_bfloat16* bG = g_lnh + (size_t)blockIdx.y * BN * DH;
    float acc[2][8][4] = {};
    mainloop(aG, DH, bG, DH, DH / BKC, sAu, sBu, acc);

    float part = 0.f;
    #pragma unroll
    for (int mi = 0; mi < 2; mi++)
        #pragma unroll
        for (int nj = 0; nj < 8; nj++) {
            part += __expf(acc[mi][nj][0] * TAU_INV);
            part += __expf(acc[mi][nj][1] * TAU_INV);
            part += __expf(acc[mi][nj][2] * TAU_INV);
            part += __expf(acc[mi][nj][3] * TAU_INV);
        }
    int b = blockIdx.x / 9;
    block_reduce_add(part, red, &g_close[b]);
}

// ---------------------------------------------------------------- finish
__global__ void finish_k(float* out) {
    __shared__ double sh[BATCH];
    int t = threadIdx.x;
    sh[t] = log(g_far[t]) - log(g_close[t]);
    __syncthreads();
    if (t == 0) {
        double s = 0.0;
        for (int i = 0; i < BATCH; i++) s += sh[i];
        out[0] = (float)(s / (double)BATCH);
    }
}

// ---------------------------------------------------------------- launch
extern "C" void kernel_launch(void* const* d_in, const int* in_sizes, int n_in,
                              void* d_out, int out_size) {
    const float* x      = (const float*)d_in[0];
    const float* conv_w = (const float*)d_in[1];
    const float* conv_b = (const float*)d_in[2];
    const float* latent = (const float*)d_in[3];
    float* out = (float*)d_out;

    init_k<<<1, 64>>>();
    im2col_k<<<(MTOT * (KDIM / 8)) / 256, 256>>>(x);
    wconv_k<<<(DH * KDIM / 8) / 256, 256>>>(conv_w);
    gemm_embed_k<<<dim3(MTOT / BM, DH / BN), NTHR>>>(conv_b);
    norm_patch_k<<<(MTOT * 32) / 256, 256>>>();
    norm_latent_k<<<(LLAT * 32) / 256, 256>>>(latent);
    far_k<<<dim3(NPAT / BM, 5, BATCH), NTHR>>>();
    close_k<<<dim3(MTOT / BM, LLAT / BN), NTHR>>>();
    finish_k<<<1, BATCH>>>(out);
}

// round 9
// speedup vs baseline: 1.2167x; 1.2167x over previous
#include <cuda_runtime.h>
#include <cuda_bf16.h>
#include <math.h>
#include <stdint.h>

// Problem constants
#define BATCH 64
#define NP 24
#define NPAT 576
#define DH 768
#define KDIM 768
#define LLAT 1024
#define HW 384
#define PSZ 16
#define TAU_INV 2.0f
#define EPSN 1e-8f
#define MTOT (BATCH*NPAT) // 36864

// GEMM tiling: 64x128 block tile, 4 warps of 32x64, BK=64, 2-stage cp.async
#define BM 64
#define BN 128
#define BKC 64
#define BKP 72            // padded smem row stride (bf16): 36-word stride, LDSM conflict-free
#define NTHR 128
#define ASTG (BM * BKP * 2)   // 9216 B per A stage
#define BSTG (BN * BKP * 2)   // 18432 B per B stage
#define SMEM_DYN (2 * (ASTG + BSTG))  // 55296 B

// Scratch
__device__ __nv_bfloat16 g_Ah[(size_t)MTOT * KDIM];        // im2col bf16
__device__ __nv_bfloat16 g_Wh[(size_t)DH * KDIM];          // conv weight bf16
__device__ float         g_pn[(size_t)MTOT * DH];          // embeddings fp32
__device__ __nv_bfloat16 g_pnh[(size_t)(MTOT + 128) * DH]; // normalized bf16 (+pad)
__device__ __nv_bfloat16 g_lnh[(size_t)LLAT * DH];         // normalized latent bf16
__device__ double g_far[BATCH];
__device__ double g_close[BATCH];

// far triangle tile list: 64-row tiles (9) x 128-col tiles (5), tiles with c-range > r-range
__constant__ int c_TI[29] = {0,0,0,0,0, 1,1,1,1,1, 2,2,2,2, 3,3,3,3, 4,4,4, 5,5,5, 6,6, 7,7, 8};
__constant__ int c_TJ[29] = {0,1,2,3,4, 0,1,2,3,4, 1,2,3,4, 1,2,3,4, 2,3,4, 2,3,4, 3,4, 3,4, 4};

// ---------------------------------------------------------------- PTX helpers
__device__ __forceinline__ void mma16816(float c[4],
    uint32_t a0, uint32_t a1, uint32_t a2, uint32_t a3,
    uint32_t b0, uint32_t b1)
{
    asm volatile(
        "mma.sync.aligned.m16n8k16.row.col.f32.bf16.bf16.f32 "
        "{%0,%1,%2,%3}, {%4,%5,%6,%7}, {%8,%9}, {%0,%1,%2,%3};\n"
        : "+f"(c[0]), "+f"(c[1]), "+f"(c[2]), "+f"(c[3])
        : "r"(a0), "r"(a1), "r"(a2), "r"(a3), "r"(b0), "r"(b1));
}
__device__ __forceinline__ void cpa16(uint32_t dst, const void* src) {
    asm volatile("cp.async.cg.shared.global [%0], [%1], 16;\n" :: "r"(dst), "l"(src));
}
__device__ __forceinline__ void cp_commit() { asm volatile("cp.async.commit_group;\n"); }
__device__ __forceinline__ void cp_wait0()  { asm volatile("cp.async.wait_group 0;\n"); }
__device__ __forceinline__ void cp_wait1()  { asm volatile("cp.async.wait_group 1;\n"); }
__device__ __forceinline__ void ldsm4(uint32_t& r0, uint32_t& r1, uint32_t& r2, uint32_t& r3,
                                      uint32_t addr)
{
    asm volatile("ldmatrix.sync.aligned.m8n8.x4.shared.b16 {%0,%1,%2,%3}, [%4];\n"
                 : "=r"(r0), "=r"(r1), "=r"(r2), "=r"(r3) : "r"(addr));
}

// ---------------------------------------------------------------- stage loader
// A: 64 rows x 64 k, B: 128 rows x 64 k, bf16 K-major, 16B per cp.async
__device__ __forceinline__ void load_stage(uint32_t sAu, uint32_t sBu, int stage,
    const __nv_bfloat16* aG, int ldA,
    const __nv_bfloat16* bG, int ldB, int k0, int tid)
{
    uint32_t aBase = sAu + (uint32_t)stage * ASTG;
    uint32_t bBase = sBu + (uint32_t)stage * BSTG;
    #pragma unroll
    for (int it = 0; it < 4; it++) {
        int idx = tid + it * NTHR;            // 0..511
        int row = idx >> 3, slot = idx & 7;
        cpa16(aBase + (uint32_t)(row * BKP + slot * 8) * 2,
              aG + (size_t)row * ldA + k0 + slot * 8);
    }
    #pragma unroll
    for (int it = 0; it < 8; it++) {
        int idx = tid + it * NTHR;            // 0..1023
        int row = idx >> 3, slot = idx & 7;
        cpa16(bBase + (uint32_t)(row * BKP + slot * 8) * 2,
              bG + (size_t)row * ldB + k0 + slot * 8);
    }
}

// ---------------------------------------------------------------- mainloop
// 64x128 block tile, warp tile 32x64, BK=64 chunks, 2-stage pipeline
__device__ __forceinline__ void mainloop(
    const __nv_bfloat16* __restrict__ aG, int ldA,
    const __nv_bfloat16* __restrict__ bG, int ldB,
    int nk, uint32_t sAu, uint32_t sBu, float acc[2][8][4])
{
    int tid  = threadIdx.x;
    int lane = tid & 31, warp = tid >> 5;
    int wm = (warp >> 1) * 32;     // 0,32
    int wn = (warp & 1) * 64;      // 0,64
    int arow  = lane & 15;
    int acol8 = (lane >> 4) * 8;
    int bn  = ((lane >> 4) & 1) * 8 + (lane & 7);
    int bk8 = ((lane >> 3) & 1) * 8;

    uint32_t aAddr[2], bAddr[4];
    #pragma unroll
    for (int mi = 0; mi < 2; mi++)
        aAddr[mi] = sAu + (uint32_t)((wm + mi * 16 + arow) * BKP + acol8) * 2;
    #pragma unroll
    for (int p = 0; p < 4; p++)
        bAddr[p] = sBu + (uint32_t)((wn + p * 16 + bn) * BKP + bk8) * 2;

    load_stage(sAu, sBu, 0, aG, ldA, bG, ldB, 0, tid);   cp_commit();
    load_stage(sAu, sBu, 1, aG, ldA, bG, ldB, BKC, tid); cp_commit();

    for (int kc = 0; kc < nk; kc++) {
        int buf = kc & 1;
        if (kc == nk - 1) cp_wait0(); else cp_wait1();
        __syncthreads();
        uint32_t aoff = (uint32_t)buf * ASTG;
        uint32_t boff = (uint32_t)buf * BSTG;
        #pragma unroll
        for (int ks = 0; ks < 4; ks++) {                 // 4 x k16 sub-steps
            uint32_t ko2 = (uint32_t)ks * 32;            // 16 elems * 2 B
            uint32_t a[2][4], b[8][2];
            #pragma unroll
            for (int mi = 0; mi < 2; mi++)
                ldsm4(a[mi][0], a[mi][1], a[mi][2], a[mi][3], aAddr[mi] + aoff + ko2);
            #pragma unroll
            for (int p = 0; p < 4; p++)
                ldsm4(b[p*2][0], b[p*2][1], b[p*2+1][0], b[p*2+1][1], bAddr[p] + boff + ko2);
            #pragma unroll
            for (int mi = 0; mi < 2; mi++)
                #pragma unroll
                for (int nj = 0; nj < 8; nj++)
                    mma16816(acc[mi][nj], a[mi][0], a[mi][1], a[mi][2], a[mi][3],
                             b[nj][0], b[nj][1]);
        }
        __syncthreads();                                 // done reading stage buf
        if (kc + 2 < nk) {
            load_stage(sAu, sBu, buf, aG, ldA, bG, ldB, (kc + 2) * BKC, tid);
            cp_commit();
        }
    }
}

// block reduce (128 threads) -> double atomic
__device__ __forceinline__ void block_reduce_add(float part, float* red, double* gout) {
    int tid = threadIdx.x, lane = tid & 31, warp = tid >> 5;
    #pragma unroll
    for (int o = 16; o; o >>= 1) part += __shfl_xor_sync(0xffffffffu, part, o);
    if (lane == 0) red[warp] = part;
    __syncthreads();
    if (tid == 0) {
        float s = red[0] + red[1] + red[2] + red[3];
        atomicAdd(gout, (double)s);
    }
}

// ---------------------------------------------------------------- init
__global__ void init_k() {
    int t = threadIdx.x;
    if (t < BATCH) { g_far[t] = 0.0; g_close[t] = 0.0; }
}

// ---------------------------------------------------------------- im2col -> bf16
__global__ void im2col_k(const float* __restrict__ x) {
    int idx = blockIdx.x * 256 + threadIdx.x;
    int kq  = idx % (KDIM / 8);
    int row = idx / (KDIM / 8);
    int k  = kq * 8;
    int kw = k & 15, kh = (k >> 4) & 15, c = k >> 8;
    int pw = row % NP; int t = row / NP; int ph = t % NP; int b = t / NP;
    const float* src = x + ((size_t)(b*3 + c)*HW + ph*PSZ + kh)*HW + pw*PSZ + kw;
    float4 v0 = *(const float4*)(src);
    float4 v1 = *(const float4*)(src + 4);
    __nv_bfloat16 o[8];
    o[0]=__float2bfloat16_rn(v0.x); o[1]=__float2bfloat16_rn(v0.y);
    o[2]=__float2bfloat16_rn(v0.z); o[3]=__float2bfloat16_rn(v0.w);
    o[4]=__float2bfloat16_rn(v1.x); o[5]=__float2bfloat16_rn(v1.y);
    o[6]=__float2bfloat16_rn(v1.z); o[7]=__float2bfloat16_rn(v1.w);
    *(int4*)(g_Ah + (size_t)row * KDIM + k) = *(int4*)o;
}

// ---------------------------------------------------------------- W -> bf16
__global__ void wconv_k(const float* __restrict__ W) {
    int idx = blockIdx.x * 256 + threadIdx.x;
    const float4* src = (const float4*)(W + (size_t)idx * 8);
    float4 v0 = src[0], v1 = src[1];
    __nv_bfloat16 o[8];
    o[0]=__float2bfloat16_rn(v0.x); o[1]=__float2bfloat16_rn(v0.y);
    o[2]=__float2bfloat16_rn(v0.z); o[3]=__float2bfloat16_rn(v0.w);
    o[4]=__float2bfloat16_rn(v1.x); o[5]=__float2bfloat16_rn(v1.y);
    o[6]=__float2bfloat16_rn(v1.z); o[7]=__float2bfloat16_rn(v1.w);
    *(int4*)(g_Wh + (size_t)idx * 8) = *(int4*)o;
}

// ---------------------------------------------------------------- GEMM embed
__global__ __launch_bounds__(NTHR, 4) void gemm_embed_k(const float* __restrict__ bias) {
    extern __shared__ __align__(16) char dsm[];
    uint32_t sAu = (uint32_t)__cvta_generic_to_shared(dsm);
    uint32_t sBu = sAu + 2u * ASTG;
    const __nv_bfloat16* aG = g_Ah + (size_t)blockIdx.x * BM * KDIM;
    const __nv_bfloat16* bG = g_Wh + (size_t)blockIdx.y * BN * KDIM;
    float acc[2][8][4] = {};
    mainloop(aG, KDIM, bG, KDIM, KDIM / BKC, sAu, sBu, acc);

    int lane = threadIdx.x & 31, warp = threadIdx.x >> 5;
    int wm = (warp >> 1) * 32, wn = (warp & 1) * 64;
    int g = lane >> 2, lt = lane & 3;
    int rowB = blockIdx.x * BM + wm;
    int colB = blockIdx.y * BN + wn;
    #pragma unroll
    for (int mi = 0; mi < 2; mi++)
        #pragma unroll
        for (int nj = 0; nj < 8; nj++) {
            int col = colB + nj * 8 + lt * 2;
            float b0 = bias[col], b1 = bias[col + 1];
            int r0 = rowB + mi * 16 + g;
            float2 v0 = { acc[mi][nj][0] + b0, acc[mi][nj][1] + b1 };
            float2 v1 = { acc[mi][nj][2] + b0, acc[mi][nj][3] + b1 };
            *(float2*)(g_pn + (size_t)r0 * DH + col)       = v0;
            *(float2*)(g_pn + (size_t)(r0 + 8) * DH + col) = v1;
        }
}

// ---------------------------------------------------------------- L2 normalize
__global__ void norm_patch_k() {
    int gw = (blockIdx.x * blockDim.x + threadIdx.x) >> 5;
    int lane = threadIdx.x & 31;
    if (gw >= MTOT) return;
    const float4* r = (const float4*)(g_pn + (size_t)gw * DH);
    ushort4* dst = (ushort4*)(g_pnh + (size_t)gw * DH);
    float s = 0.f; float4 v[6];
    #pragma unroll
    for (int i = 0; i < 6; i++) {
        v[i] = r[lane + 32*i];
        s += v[i].x*v[i].x + v[i].y*v[i].y + v[i].z*v[i].z + v[i].w*v[i].w;
    }
    #pragma unroll
    for (int o = 16; o; o >>= 1) s += __shfl_xor_sync(0xffffffffu, s, o);
    float inv = 1.0f / fmaxf(sqrtf(s), EPSN);
    #pragma unroll
    for (int i = 0; i < 6; i++) {
        __nv_bfloat16 o4[4];
        o4[0] = __float2bfloat16_rn(v[i].x * inv);
        o4[1] = __float2bfloat16_rn(v[i].y * inv);
        o4[2] = __float2bfloat16_rn(v[i].z * inv);
        o4[3] = __float2bfloat16_rn(v[i].w * inv);
        dst[lane + 32*i] = *(ushort4*)o4;
    }
}

__global__ void norm_latent_k(const float* __restrict__ latent) {
    int gw = (blockIdx.x * blockDim.x + threadIdx.x) >> 5;
    int lane = threadIdx.x & 31;
    if (gw >= LLAT) return;
    const float4* src = (const float4*)(latent + (size_t)gw * DH);
    ushort4* dst = (ushort4*)(g_lnh + (size_t)gw * DH);
    float s = 0.f; float4 v[6];
    #pragma unroll
    for (int i = 0; i < 6; i++) {
        v[i] = src[lane + 32*i];
        s += v[i].x*v[i].x + v[i].y*v[i].y + v[i].z*v[i].z + v[i].w*v[i].w;
    }
    #pragma unroll
    for (int o = 16; o; o >>= 1) s += __shfl_xor_sync(0xffffffffu, s, o);
    float inv = 1.0f / fmaxf(sqrtf(s), EPSN);
    #pragma unroll
    for (int i = 0; i < 6; i++) {
        __nv_bfloat16 o4[4];
        o4[0] = __float2bfloat16_rn(v[i].x * inv);
        o4[1] = __float2bfloat16_rn(v[i].y * inv);
        o4[2] = __float2bfloat16_rn(v[i].z * inv);
        o4[3] = __float2bfloat16_rn(v[i].w * inv);
        dst[lane + 32*i] = *(ushort4*)o4;
    }
}

// ---------------------------------------------------------------- far
// triangle tiles only (29 per batch); element mask c>r contributes 2*exp
__global__ __launch_bounds__(NTHR, 4) void far_k() {
    int t = blockIdx.x, b = blockIdx.z;
    int tI = c_TI[t], tJ = c_TJ[t];
    extern __shared__ __align__(16) char dsm[];
    __shared__ float red[4];
    uint32_t sAu = (uint32_t)__cvta_generic_to_shared(dsm);
    uint32_t sBu = sAu + 2u * ASTG;
    const __nv_bfloat16* aG = g_pnh + ((size_t)b * NPAT + tI * BM) * DH;
    const __nv_bfloat16* bG = g_pnh + ((size_t)b * NPAT + tJ * BN) * DH;
    float acc[2][8][4] = {};
    mainloop(aG, DH, bG, DH, DH / BKC, sAu, sBu, acc);

    int lane = threadIdx.x & 31, warp = threadIdx.x >> 5;
    int wm = (warp >> 1) * 32, wn = (warp & 1) * 64;
    int g = lane >> 2, lt = lane & 3;
    float part = 0.f;
    #pragma unroll
    for (int mi = 0; mi < 2; mi++)
        #pragma unroll
        for (int nj = 0; nj < 8; nj++) {
            int r0 = tI * BM + wm + mi * 16 + g;
            int c0 = tJ * BN + wn + nj * 8 + lt * 2;
            float e0 = __expf(acc[mi][nj][0] * TAU_INV);
            float e1 = __expf(acc[mi][nj][1] * TAU_INV);
            float e2 = __expf(acc[mi][nj][2] * TAU_INV);
            float e3 = __expf(acc[mi][nj][3] * TAU_INV);
            part += (c0     > r0     && c0     < NPAT) ? 2.f * e0 : 0.f;
            part += (c0 + 1 > r0     && c0 + 1 < NPAT) ? 2.f * e1 : 0.f;
            part += (c0     > r0 + 8 && c0     < NPAT) ? 2.f * e2 : 0.f;
            part += (c0 + 1 > r0 + 8 && c0 + 1 < NPAT) ? 2.f * e3 : 0.f;
        }
    block_reduce_add(part, red, &g_far[b]);
}

// ---------------------------------------------------------------- close
// 36864 x 1024 GEMM; each 64-row tile lies in exactly one batch (576 = 9*64)
__global__ __launch_bounds__(NTHR, 4) void close_k() {
    extern __shared__ __align__(16) char dsm[];
    __shared__ float red[4];
    uint32_t sAu = (uint32_t)__cvta_generic_to_shared(dsm);
    uint32_t sBu = sAu + 2u * ASTG;
    const __nv_bfloat16* aG = g_pnh + (size_t)blockIdx.x * BM * DH;
    const __nv_bfloat16* bG = g_lnh + (size_t)blockIdx.y * BN * DH;
    float acc[2][8][4] = {};
    mainloop(aG, DH, bG, DH, DH / BKC, sAu, sBu, acc);

    float part = 0.f;
    #pragma unroll
    for (int mi = 0; mi < 2; mi++)
        #pragma unroll
        for (int nj = 0; nj < 8; nj++) {
            part += __expf(acc[mi][nj][0] * TAU_INV);
            part += __expf(acc[mi][nj][1] * TAU_INV);
            part += __expf(acc[mi][nj][2] * TAU_INV);
            part += __expf(acc[mi][nj][3] * TAU_INV);
        }
    int b = blockIdx.x / 9;
    block_reduce_add(part, red, &g_close[b]);
}

// ---------------------------------------------------------------- finish
__global__ void finish_k(float* out) {
    __shared__ double sh[BATCH];
    int t = threadIdx.x;
    sh[t] = log(g_far[t]) - log(g_close[t]);
    __syncthreads();
    if (t == 0) {
        double s = 0.0;
        for (int i = 0; i < BATCH; i++) s += sh[i];
        out[0] = (float)(s / (double)BATCH);
    }
}

// ---------------------------------------------------------------- launch
extern "C" void kernel_launch(void* const* d_in, const int* in_sizes, int n_in,
                              void* d_out, int out_size) {
    const float* x      = (const float*)d_in[0];
    const float* conv_w = (const float*)d_in[1];
    const float* conv_b = (const float*)d_in[2];
    const float* latent = (const float*)d_in[3];
    float* out = (float*)d_out;

    // idempotent host-side attribute set (not a stream op; not captured)
    cudaFuncSetAttribute(gemm_embed_k, cudaFuncAttributeMaxDynamicSharedMemorySize, SMEM_DYN);
    cudaFuncSetAttribute(far_k,        cudaFuncAttributeMaxDynamicSharedMemorySize, SMEM_DYN);
    cudaFuncSetAttribute(close_k,      cudaFuncAttributeMaxDynamicSharedMemorySize, SMEM_DYN);

    init_k<<<1, 64>>>();
    im2col_k<<<(MTOT * (KDIM / 8)) / 256, 256>>>(x);
    wconv_k<<<(DH * KDIM / 8) / 256, 256>>>(conv_w);
    gemm_embed_k<<<dim3(MTOT / BM, DH / BN), NTHR, SMEM_DYN>>>(conv_b);
    norm_patch_k<<<(MTOT * 32) / 256, 256>>>();
    norm_latent_k<<<(LLAT * 32) / 256, 256>>>(latent);
    far_k<<<dim3(29, 1, BATCH), NTHR, SMEM_DYN>>>();
    close_k<<<dim3(MTOT / BM, LLAT / BN), NTHR, SMEM_DYN>>>();
    finish_k<<<1, BATCH>>>(out);
}

// round 10
// speedup vs baseline: 1.2329x; 1.0133x over previous
#include <cuda_runtime.h>
#include <cuda_bf16.h>
#include <math.h>
#include <stdint.h>

// Problem constants
#define BATCH 64
#define NP 24
#define NPAT 576
#define DH 768
#define KDIM 768
#define LLAT 1024
#define HW 384
#define PSZ 16
#define TAU_INV 2.0f
#define EPSN 1e-8f
#define MTOT (BATCH*NPAT) // 36864

// GEMM tiling: 64x128 block tile, 4 warps of 32x64, BK=64, 2-stage cp.async
#define BM 64
#define BN 128
#define BKC 64
#define BKP 72            // padded smem row stride (bf16): 36-word stride, LDSM conflict-free
#define NTHR 128
#define ASTG (BM * BKP * 2)   // 9216 B per A stage
#define BSTG (BN * BKP * 2)   // 18432 B per B stage
#define SMEM_DYN (2 * (ASTG + BSTG))  // 55296 B

// Scratch
__device__ __nv_bfloat16 g_Ah[(size_t)MTOT * KDIM];        // im2col bf16
__device__ __nv_bfloat16 g_Wh[(size_t)DH * KDIM];          // conv weight bf16
__device__ __nv_bfloat16 g_pne[(size_t)MTOT * DH];         // embeddings bf16 (pre-norm)
__device__ __nv_bfloat16 g_pnh[(size_t)(MTOT + 128) * DH]; // normalized bf16 (+pad)
__device__ __nv_bfloat16 g_lnh[(size_t)LLAT * DH];         // normalized latent bf16
__device__ double g_far[BATCH];
__device__ double g_close[BATCH];

// far triangle tile list: 64-row tiles (9) x 128-col tiles (5), tiles containing c>r
__constant__ int c_TI[29] = {0,0,0,0,0, 1,1,1,1,1, 2,2,2,2, 3,3,3,3, 4,4,4, 5,5,5, 6,6, 7,7, 8};
__constant__ int c_TJ[29] = {0,1,2,3,4, 0,1,2,3,4, 1,2,3,4, 1,2,3,4, 2,3,4, 2,3,4, 3,4, 3,4, 4};

// ---------------------------------------------------------------- PTX helpers
__device__ __forceinline__ void mma16816(float c[4],
    uint32_t a0, uint32_t a1, uint32_t a2, uint32_t a3,
    uint32_t b0, uint32_t b1)
{
    asm volatile(
        "mma.sync.aligned.m16n8k16.row.col.f32.bf16.bf16.f32 "
        "{%0,%1,%2,%3}, {%4,%5,%6,%7}, {%8,%9}, {%0,%1,%2,%3};\n"
        : "+f"(c[0]), "+f"(c[1]), "+f"(c[2]), "+f"(c[3])
        : "r"(a0), "r"(a1), "r"(a2), "r"(a3), "r"(b0), "r"(b1));
}
__device__ __forceinline__ void cpa16(uint32_t dst, const void* src) {
    asm volatile("cp.async.cg.shared.global [%0], [%1], 16;\n" :: "r"(dst), "l"(src));
}
__device__ __forceinline__ void cp_commit() { asm volatile("cp.async.commit_group;\n"); }
__device__ __forceinline__ void cp_wait0()  { asm volatile("cp.async.wait_group 0;\n"); }
__device__ __forceinline__ void cp_wait1()  { asm volatile("cp.async.wait_group 1;\n"); }
__device__ __forceinline__ void ldsm4(uint32_t& r0, uint32_t& r1, uint32_t& r2, uint32_t& r3,
                                      uint32_t addr)
{
    asm volatile("ldmatrix.sync.aligned.m8n8.x4.shared.b16 {%0,%1,%2,%3}, [%4];\n"
                 : "=r"(r0), "=r"(r1), "=r"(r2), "=r"(r3) : "r"(addr));
}

// ---------------------------------------------------------------- stage loader
__device__ __forceinline__ void load_stage(uint32_t sAu, uint32_t sBu, int stage,
    const __nv_bfloat16* aG, int ldA,
    const __nv_bfloat16* bG, int ldB, int k0, int tid)
{
    uint32_t aBase = sAu + (uint32_t)stage * ASTG;
    uint32_t bBase = sBu + (uint32_t)stage * BSTG;
    #pragma unroll
    for (int it = 0; it < 4; it++) {
        int idx = tid + it * NTHR;            // 0..511
        int row = idx >> 3, slot = idx & 7;
        cpa16(aBase + (uint32_t)(row * BKP + slot * 8) * 2,
              aG + (size_t)row * ldA + k0 + slot * 8);
    }
    #pragma unroll
    for (int it = 0; it < 8; it++) {
        int idx = tid + it * NTHR;            // 0..1023
        int row = idx >> 3, slot = idx & 7;
        cpa16(bBase + (uint32_t)(row * BKP + slot * 8) * 2,
              bG + (size_t)row * ldB + k0 + slot * 8);
    }
}

// ---------------------------------------------------------------- mainloop
// 64x128 block tile, warp tile 32x64, BK=64 chunks, 2-stage smem pipeline,
// fragment-level double buffering across the 4 k16 sub-steps.
__device__ __forceinline__ void mainloop(
    const __nv_bfloat16* __restrict__ aG, int ldA,
    const __nv_bfloat16* __restrict__ bG, int ldB,
    int nk, uint32_t sAu, uint32_t sBu, float acc[2][8][4])
{
    int tid  = threadIdx.x;
    int lane = tid & 31, warp = tid >> 5;
    int wm = (warp >> 1) * 32;     // 0,32
    int wn = (warp & 1) * 64;      // 0,64
    int arow  = lane & 15;
    int acol8 = (lane >> 4) * 8;
    int bn  = ((lane >> 4) & 1) * 8 + (lane & 7);
    int bk8 = ((lane >> 3) & 1) * 8;

    uint32_t aAddr[2], bAddr[4];
    #pragma unroll
    for (int mi = 0; mi < 2; mi++)
        aAddr[mi] = sAu + (uint32_t)((wm + mi * 16 + arow) * BKP + acol8) * 2;
    #pragma unroll
    for (int p = 0; p < 4; p++)
        bAddr[p] = sBu + (uint32_t)((wn + p * 16 + bn) * BKP + bk8) * 2;

    load_stage(sAu, sBu, 0, aG, ldA, bG, ldB, 0, tid);   cp_commit();
    load_stage(sAu, sBu, 1, aG, ldA, bG, ldB, BKC, tid); cp_commit();

    uint32_t af[2][2][4], bf[2][8][2];   // double-buffered fragments

    for (int kc = 0; kc < nk; kc++) {
        int buf = kc & 1;
        if (kc == nk - 1) cp_wait0(); else cp_wait1();
        __syncthreads();
        uint32_t aoff = (uint32_t)buf * ASTG;
        uint32_t boff = (uint32_t)buf * BSTG;

        // prime sub-step 0
        #pragma unroll
        for (int mi = 0; mi < 2; mi++)
            ldsm4(af[0][mi][0], af[0][mi][1], af[0][mi][2], af[0][mi][3],
                  aAddr[mi] + aoff);
        #pragma unroll
        for (int p = 0; p < 4; p++)
            ldsm4(bf[0][p*2][0], bf[0][p*2][1], bf[0][p*2+1][0], bf[0][p*2+1][1],
                  bAddr[p] + boff);

        #pragma unroll
        for (int ks = 0; ks < 4; ks++) {
            int cur = ks & 1, nxt = cur ^ 1;
            if (ks < 3) {                       // prefetch next sub-step's fragments
                uint32_t ko2 = (uint32_t)(ks + 1) * 32;
                #pragma unroll
                for (int mi = 0; mi < 2; mi++)
                    ldsm4(af[nxt][mi][0], af[nxt][mi][1], af[nxt][mi][2], af[nxt][mi][3],
                          aAddr[mi] + aoff + ko2);
                #pragma unroll
                for (int p = 0; p < 4; p++)
                    ldsm4(bf[nxt][p*2][0], bf[nxt][p*2][1], bf[nxt][p*2+1][0], bf[nxt][p*2+1][1],
                          bAddr[p] + boff + ko2);
            }
            #pragma unroll
            for (int mi = 0; mi < 2; mi++)
                #pragma unroll
                for (int nj = 0; nj < 8; nj++)
                    mma16816(acc[mi][nj],
                             af[cur][mi][0], af[cur][mi][1], af[cur][mi][2], af[cur][mi][3],
                             bf[cur][nj][0], bf[cur][nj][1]);
        }
        __syncthreads();                         // stage buf fully consumed
        if (kc + 2 < nk) {
            load_stage(sAu, sBu, buf, aG, ldA, bG, ldB, (kc + 2) * BKC, tid);
            cp_commit();
        }
    }
}

// block reduce (128 threads) -> double atomic
__device__ __forceinline__ void block_reduce_add(float part, float* red, double* gout) {
    int tid = threadIdx.x, lane = tid & 31, warp = tid >> 5;
    #pragma unroll
    for (int o = 16; o; o >>= 1) part += __shfl_xor_sync(0xffffffffu, part, o);
    if (lane == 0) red[warp] = part;
    __syncthreads();
    if (tid == 0) {
        float s = red[0] + red[1] + red[2] + red[3];
        atomicAdd(gout, (double)s);
    }
}

// ---------------------------------------------------------------- init
__global__ void init_k() {
    int t = threadIdx.x;
    if (t < BATCH) { g_far[t] = 0.0; g_close[t] = 0.0; }
}

// ---------------------------------------------------------------- im2col -> bf16
__global__ void im2col_k(const float* __restrict__ x) {
    int idx = blockIdx.x * 256 + threadIdx.x;
    int kq  = idx % (KDIM / 8);
    int row = idx / (KDIM / 8);
    int k  = kq * 8;
    int kw = k & 15, kh = (k >> 4) & 15, c = k >> 8;
    int pw = row % NP; int t = row / NP; int ph = t % NP; int b = t / NP;
    const float* src = x + ((size_t)(b*3 + c)*HW + ph*PSZ + kh)*HW + pw*PSZ + kw;
    float4 v0 = *(const float4*)(src);
    float4 v1 = *(const float4*)(src + 4);
    __nv_bfloat16 o[8];
    o[0]=__float2bfloat16_rn(v0.x); o[1]=__float2bfloat16_rn(v0.y);
    o[2]=__float2bfloat16_rn(v0.z); o[3]=__float2bfloat16_rn(v0.w);
    o[4]=__float2bfloat16_rn(v1.x); o[5]=__float2bfloat16_rn(v1.y);
    o[6]=__float2bfloat16_rn(v1.z); o[7]=__float2bfloat16_rn(v1.w);
    *(int4*)(g_Ah + (size_t)row * KDIM + k) = *(int4*)o;
}

// ---------------------------------------------------------------- W -> bf16
__global__ void wconv_k(const float* __restrict__ W) {
    int idx = blockIdx.x * 256 + threadIdx.x;
    const float4* src = (const float4*)(W + (size_t)idx * 8);
    float4 v0 = src[0], v1 = src[1];
    __nv_bfloat16 o[8];
    o[0]=__float2bfloat16_rn(v0.x); o[1]=__float2bfloat16_rn(v0.y);
    o[2]=__float2bfloat16_rn(v0.z); o[3]=__float2bfloat16_rn(v0.w);
    o[4]=__float2bfloat16_rn(v1.x); o[5]=__float2bfloat16_rn(v1.y);
    o[6]=__float2bfloat16_rn(v1.z); o[7]=__float2bfloat16_rn(v1.w);
    *(int4*)(g_Wh + (size_t)idx * 8) = *(int4*)o;
}

// ---------------------------------------------------------------- GEMM embed (bf16 out)
__global__ __launch_bounds__(NTHR, 3) void gemm_embed_k(const float* __restrict__ bias) {
    extern __shared__ __align__(16) char dsm[];
    uint32_t sAu = (uint32_t)__cvta_generic_to_shared(dsm);
    uint32_t sBu = sAu + 2u * ASTG;
    const __nv_bfloat16* aG = g_Ah + (size_t)blockIdx.x * BM * KDIM;
    const __nv_bfloat16* bG = g_Wh + (size_t)blockIdx.y * BN * KDIM;
    float acc[2][8][4] = {};
    mainloop(aG, KDIM, bG, KDIM, KDIM / BKC, sAu, sBu, acc);

    int lane = threadIdx.x & 31, warp = threadIdx.x >> 5;
    int wm = (warp >> 1) * 32, wn = (warp & 1) * 64;
    int g = lane >> 2, lt = lane & 3;
    int rowB = blockIdx.x * BM + wm;
    int colB = blockIdx.y * BN + wn;
    #pragma unroll
    for (int mi = 0; mi < 2; mi++)
        #pragma unroll
        for (int nj = 0; nj < 8; nj++) {
            int col = colB + nj * 8 + lt * 2;
            float b0 = bias[col], b1 = bias[col + 1];
            int r0 = rowB + mi * 16 + g;
            __nv_bfloat16 p0[2] = { __float2bfloat16_rn(acc[mi][nj][0] + b0),
                                    __float2bfloat16_rn(acc[mi][nj][1] + b1) };
            __nv_bfloat16 p1[2] = { __float2bfloat16_rn(acc[mi][nj][2] + b0),
                                    __float2bfloat16_rn(acc[mi][nj][3] + b1) };
            *(uint32_t*)(g_pne + (size_t)r0 * DH + col)       = *(uint32_t*)p0;
            *(uint32_t*)(g_pne + (size_t)(r0 + 8) * DH + col) = *(uint32_t*)p1;
        }
}

// ---------------------------------------------------------------- L2 normalize (bf16 in/out)
__global__ void norm_patch_k() {
    int gw = (blockIdx.x * blockDim.x + threadIdx.x) >> 5;
    int lane = threadIdx.x & 31;
    if (gw >= MTOT) return;
    const ushort4* src = (const ushort4*)(g_pne + (size_t)gw * DH);  // 8 bf16 per ushort4? no: 4
    ushort4* dst = (ushort4*)(g_pnh + (size_t)gw * DH);
    float s = 0.f;
    ushort4 v[6];
    float f[24];
    #pragma unroll
    for (int i = 0; i < 6; i++) {
        v[i] = src[lane + 32*i];
        f[i*4+0] = __bfloat162float(*(const __nv_bfloat16*)&v[i].x);
        f[i*4+1] = __bfloat162float(*(const __nv_bfloat16*)&v[i].y);
        f[i*4+2] = __bfloat162float(*(const __nv_bfloat16*)&v[i].z);
        f[i*4+3] = __bfloat162float(*(const __nv_bfloat16*)&v[i].w);
        s += f[i*4]*f[i*4] + f[i*4+1]*f[i*4+1] + f[i*4+2]*f[i*4+2] + f[i*4+3]*f[i*4+3];
    }
    #pragma unroll
    for (int o = 16; o; o >>= 1) s += __shfl_xor_sync(0xffffffffu, s, o);
    float inv = 1.0f / fmaxf(sqrtf(s), EPSN);
    #pragma unroll
    for (int i = 0; i < 6; i++) {
        __nv_bfloat16 o4[4];
        o4[0] = __float2bfloat16_rn(f[i*4+0] * inv);
        o4[1] = __float2bfloat16_rn(f[i*4+1] * inv);
        o4[2] = __float2bfloat16_rn(f[i*4+2] * inv);
        o4[3] = __float2bfloat16_rn(f[i*4+3] * inv);
        dst[lane + 32*i] = *(ushort4*)o4;
    }
}

__global__ void norm_latent_k(const float* __restrict__ latent) {
    int gw = (blockIdx.x * blockDim.x + threadIdx.x) >> 5;
    int lane = threadIdx.x & 31;
    if (gw >= LLAT) return;
    const float4* src = (const float4*)(latent + (size_t)gw * DH);
    ushort4* dst = (ushort4*)(g_lnh + (size_t)gw * DH);
    float s = 0.f; float4 v[6];
    #pragma unroll
    for (int i = 0; i < 6; i++) {
        v[i] = src[lane + 32*i];
        s += v[i].x*v[i].x + v[i].y*v[i].y + v[i].z*v[i].z + v[i].w*v[i].w;
    }
    #pragma unroll
    for (int o = 16; o; o >>= 1) s += __shfl_xor_sync(0xffffffffu, s, o);
    float inv = 1.0f / fmaxf(sqrtf(s), EPSN);
    #pragma unroll
    for (int i = 0; i < 6; i++) {
        __nv_bfloat16 o4[4];
        o4[0] = __float2bfloat16_rn(v[i].x * inv);
        o4[1] = __float2bfloat16_rn(v[i].y * inv);
        o4[2] = __float2bfloat16_rn(v[i].z * inv);
        o4[3] = __float2bfloat16_rn(v[i].w * inv);
        dst[lane + 32*i] = *(ushort4*)o4;
    }
}

// ---------------------------------------------------------------- far
// triangle tiles only (29 per batch); element mask c>r contributes 2*exp
__global__ __launch_bounds__(NTHR, 3) void far_k() {
    int t = blockIdx.x, b = blockIdx.z;
    int tI = c_TI[t], tJ = c_TJ[t];
    extern __shared__ __align__(16) char dsm[];
    __shared__ float red[4];
    uint32_t sAu = (uint32_t)__cvta_generic_to_shared(dsm);
    uint32_t sBu = sAu + 2u * ASTG;
    const __nv_bfloat16* aG = g_pnh + ((size_t)b * NPAT + tI * BM) * DH;
    const __nv_bfloat16* bG = g_pnh + ((size_t)b * NPAT + tJ * BN) * DH;
    float acc[2][8][4] = {};
    mainloop(aG, DH, bG, DH, DH / BKC, sAu, sBu, acc);

    int lane = threadIdx.x & 31, warp = threadIdx.x >> 5;
    int wm = (warp >> 1) * 32, wn = (warp & 1) * 64;
    int g = lane >> 2, lt = lane & 3;
    float part = 0.f;
    #pragma unroll
    for (int mi = 0; mi < 2; mi++)
        #pragma unroll
        for (int nj = 0; nj < 8; nj++) {
            int r0 = tI * BM + wm + mi * 16 + g;
            int c0 = tJ * BN + wn + nj * 8 + lt * 2;
            float e0 = __expf(acc[mi][nj][0] * TAU_INV);
            float e1 = __expf(acc[mi][nj][1] * TAU_INV);
            float e2 = __expf(acc[mi][nj][2] * TAU_INV);
            float e3 = __expf(acc[mi][nj][3] * TAU_INV);
            part += (c0     > r0     && c0     < NPAT) ? 2.f * e0 : 0.f;
            part += (c0 + 1 > r0     && c0 + 1 < NPAT) ? 2.f * e1 : 0.f;
            part += (c0     > r0 + 8 && c0     < NPAT) ? 2.f * e2 : 0.f;
            part += (c0 + 1 > r0 + 8 && c0 + 1 < NPAT) ? 2.f * e3 : 0.f;
        }
    block_reduce_add(part, red, &g_far[b]);
}

// ---------------------------------------------------------------- close
__global__ __launch_bounds__(NTHR, 3) void close_k() {
    extern __shared__ __align__(16) char dsm[];
    __shared__ float red[4];
    uint32_t sAu = (uint32_t)__cvta_generic_to_shared(dsm);
    uint32_t sBu = sAu + 2u * ASTG;
    const __nv_bfloat16* aG = g_pnh + (size_t)blockIdx.x * BM * DH;
    const __nv_bfloat16* bG = g_lnh + (size_t)blockIdx.y * BN * DH;
    float acc[2][8][4] = {};
    mainloop(aG, DH, bG, DH, DH / BKC, sAu, sBu, acc);

    float part = 0.f;
    #pragma unroll
    for (int mi = 0; mi < 2; mi++)
        #pragma unroll
        for (int nj = 0; nj < 8; nj++) {
            part += __expf(acc[mi][nj][0] * TAU_INV);
            part += __expf(acc[mi][nj][1] * TAU_INV);
            part += __expf(acc[mi][nj][2] * TAU_INV);
            part += __expf(acc[mi][nj][3] * TAU_INV);
        }
    int b = blockIdx.x / 9;
    block_reduce_add(part, red, &g_close[b]);
}

// ---------------------------------------------------------------- finish
__global__ void finish_k(float* out) {
    __shared__ double sh[BATCH];
    int t = threadIdx.x;
    sh[t] = log(g_far[t]) - log(g_close[t]);
    __syncthreads();
    if (t == 0) {
        double s = 0.0;
        for (int i = 0; i < BATCH; i++) s += sh[i];
        out[0] = (float)(s / (double)BATCH);
    }
}

// ---------------------------------------------------------------- launch
extern "C" void kernel_launch(void* const* d_in, const int* in_sizes, int n_in,
                              void* d_out, int out_size) {
    const float* x      = (const float*)d_in[0];
    const float* conv_w = (const float*)d_in[1];
    const float* conv_b = (const float*)d_in[2];
    const float* latent = (const float*)d_in[3];
    float* out = (float*)d_out;

    cudaFuncSetAttribute(gemm_embed_k, cudaFuncAttributeMaxDynamicSharedMemorySize, SMEM_DYN);
    cudaFuncSetAttribute(far_k,        cudaFuncAttributeMaxDynamicSharedMemorySize, SMEM_DYN);
    cudaFuncSetAttribute(close_k,      cudaFuncAttributeMaxDynamicSharedMemorySize, SMEM_DYN);

    init_k<<<1, 64>>>();
    im2col_k<<<(MTOT * (KDIM / 8)) / 256, 256>>>(x);
    wconv_k<<<(DH * KDIM / 8) / 256, 256>>>(conv_w);
    gemm_embed_k<<<dim3(MTOT / BM, DH / BN), NTHR, SMEM_DYN>>>(conv_b);
    norm_patch_k<<<(MTOT * 32) / 256, 256>>>();
    norm_latent_k<<<(LLAT * 32) / 256, 256>>>(latent);
    far_k<<<dim3(29, 1, BATCH), NTHR, SMEM_DYN>>>();
    close_k<<<dim3(MTOT / BM, LLAT / BN), NTHR, SMEM_DYN>>>();
    finish_k<<<1, BATCH>>>(out);
}